// round 13
// baseline (speedup 1.0000x reference)
#include <cuda_runtime.h>

typedef unsigned long long u64;

#define BETA 0.95f
#define THRV 1.0f
#define KC   512              // fc1: two 512-halves folded; K=512 stays pure chain

static const int T_STEPS = 10;
static const int MAXB = 16384, MAXH = 512, MAXD = 1024;

// ---- persistent state (device globals; no runtime allocation allowed) ----
__device__ float g_cur1[MAXB * MAXH];   // fc1(x), computed once per launch
__device__ float g_m1[MAXB * MAXH];
__device__ float g_m2[MAXB * MAXH];
__device__ float g_m3[MAXB * MAXD];
__device__ float g_s1[MAXB * MAXH];
__device__ float g_s2[MAXB * MAXH];

// ---- f32x2 packed math (lane-wise identical rounding to scalar ops) ----
__device__ __forceinline__ float2 upk2(u64 v) {
    float2 f;
    asm("mov.b64 {%0, %1}, %2;" : "=f"(f.x), "=f"(f.y) : "l"(v));
    return f;
}
__device__ __forceinline__ void ffma2(u64& d, u64 a, u64 b) {
    asm("fma.rn.f32x2 %0, %1, %2, %0;" : "+l"(d) : "l"(a), "l"(b));
}
__device__ __forceinline__ void fadd2(u64& d, u64 a) {
    asm("add.rn.f32x2 %0, %0, %1;" : "+l"(d) : "l"(a));
}

// LIF update, NO FMA contraction: m' = rn(rn(rn(beta*m) + cur) - reset)
__device__ __forceinline__ void lif_step(float& m, float cur, float& s) {
    float reset = (m > THRV) ? THRV : 0.0f;   // reset uses PREVIOUS mem
    float t0 = __fmul_rn(BETA, m);
    float t1 = __fadd_rn(t0, cur);
    m = __fsub_rn(t1, reset);
    s = (m > THRV) ? 1.0f : 0.0f;
}

// ============================================================================
// Fused GEMM:  C[M,N] = A[M,K] @ W[N,K]^T (+bias) -> epilogue per MODE
//   MODE 0: write cur     MODE 1: LIF -> Mst,Sout    MODE 2: LIF -> Oacc
// Tile BM=128, BN=128, BK=16, 256 threads, 8x8 outputs/thread.
// K-HALVES ORDERING: per output, FMA chain from zero within each k-panel of
// KC=512, panels folded sequentially with one rounded add. For K<=512 this is
// bitwise a single pure ascending-k chain (fold adds exact zero).
// FFMA2 lanes are packed over ROWS, so each lane is bitwise a scalar chain.
// ============================================================================
template<int MODE>
__global__ __launch_bounds__(256)
void gemm_lif(const float* __restrict__ A, const float* __restrict__ W,
              const float* __restrict__ bias,
              float* __restrict__ Ccur,
              float* __restrict__ Mst,
              float* __restrict__ Sout,
              float* __restrict__ Oacc,
              float outScale,
              int M, int N, int K)
{
    __shared__ float As[16][128];     // As[k][m]
    __shared__ float Bs[16][256];     // Bs[k][2n], Bs[k][2n+1] = W[n][k] (dup)

    const int tid = threadIdx.x;
    const int tx  = tid & 15;   // column group 0..15
    const int ty  = tid >> 4;   // row group    0..15

    const int bm = blockIdx.y * 128;
    const int bn = blockIdx.x * 128;

    const int lr = tid >> 2;          // 0..63
    const int lk = (tid & 3) << 2;    // 0,4,8,12

    u64 accC[4][8];   // current-panel chains (f32x2 over row pairs)
    u64 accT[4][8];   // folded total
    #pragma unroll
    for (int i = 0; i < 4; i++)
        #pragma unroll
        for (int j = 0; j < 8; j++) { accC[i][j] = 0ull; accT[i][j] = 0ull; }

    for (int k0 = 0; k0 < K; k0 += 16) {
        float4 a0 = *(const float4*)(A + (size_t)(bm + lr)      * K + k0 + lk);
        float4 a1 = *(const float4*)(A + (size_t)(bm + lr + 64) * K + k0 + lk);
        float4 w0 = *(const float4*)(W + (size_t)(bn + lr)      * K + k0 + lk);
        float4 w1 = *(const float4*)(W + (size_t)(bn + lr + 64) * K + k0 + lk);

        __syncthreads();   // previous tile's compute done before overwrite
        As[lk+0][lr]      = a0.x; As[lk+1][lr]      = a0.y;
        As[lk+2][lr]      = a0.z; As[lk+3][lr]      = a0.w;
        As[lk+0][lr+64]   = a1.x; As[lk+1][lr+64]   = a1.y;
        As[lk+2][lr+64]   = a1.z; As[lk+3][lr+64]   = a1.w;

        int c0 = 2 * lr;
        int c1 = 2 * (lr + 64);
        Bs[lk+0][c0] = w0.x; Bs[lk+0][c0+1] = w0.x;
        Bs[lk+1][c0] = w0.y; Bs[lk+1][c0+1] = w0.y;
        Bs[lk+2][c0] = w0.z; Bs[lk+2][c0+1] = w0.z;
        Bs[lk+3][c0] = w0.w; Bs[lk+3][c0+1] = w0.w;
        Bs[lk+0][c1] = w1.x; Bs[lk+0][c1+1] = w1.x;
        Bs[lk+1][c1] = w1.y; Bs[lk+1][c1+1] = w1.y;
        Bs[lk+2][c1] = w1.z; Bs[lk+2][c1+1] = w1.z;
        Bs[lk+3][c1] = w1.w; Bs[lk+3][c1+1] = w1.w;
        __syncthreads();

        #pragma unroll
        for (int k = 0; k < 16; k++) {
            ulonglong2 av0 = *(const ulonglong2*)&As[k][ty * 8];
            ulonglong2 av1 = *(const ulonglong2*)&As[k][ty * 8 + 4];
            u64 ap[4] = { av0.x, av0.y, av1.x, av1.y };
            ulonglong2 bv0 = *(const ulonglong2*)&Bs[k][8 * tx];
            ulonglong2 bv1 = *(const ulonglong2*)&Bs[k][8 * tx + 4];
            ulonglong2 bv2 = *(const ulonglong2*)&Bs[k][128 + 8 * tx];
            ulonglong2 bv3 = *(const ulonglong2*)&Bs[k][128 + 8 * tx + 4];
            u64 bd[8] = { bv0.x, bv0.y, bv1.x, bv1.y,
                          bv2.x, bv2.y, bv3.x, bv3.y };
            #pragma unroll
            for (int ip = 0; ip < 4; ip++)
                #pragma unroll
                for (int j = 0; j < 8; j++)
                    ffma2(accC[ip][j], ap[ip], bd[j]);
        }

        // k-panel boundary: fold chunk into total with one rounded add
        if (((k0 + 16) % KC) == 0) {
            #pragma unroll
            for (int ip = 0; ip < 4; ip++)
                #pragma unroll
                for (int j = 0; j < 8; j++) {
                    fadd2(accT[ip][j], accC[ip][j]);
                    accC[ip][j] = 0ull;
                }
        }
    }

    // final fold (adds exact zero when K is a multiple of KC)
    #pragma unroll
    for (int ip = 0; ip < 4; ip++)
        #pragma unroll
        for (int j = 0; j < 8; j++)
            fadd2(accT[ip][j], accC[ip][j]);

    // ---- epilogue ----
    const int col0 = bn + 4 * tx;
    const int col1 = col0 + 64;
    float4 bb0 = *(const float4*)(bias + col0);
    float4 bb1 = *(const float4*)(bias + col1);

    #pragma unroll
    for (int ip = 0; ip < 4; ip++) {
        float2 p[8];
        #pragma unroll
        for (int j = 0; j < 8; j++) p[j] = upk2(accT[ip][j]);

        #pragma unroll
        for (int h = 0; h < 2; h++) {
            const int r = bm + ty * 8 + 2 * ip + h;
            float v0 = h ? p[0].y : p[0].x;
            float v1 = h ? p[1].y : p[1].x;
            float v2 = h ? p[2].y : p[2].x;
            float v3 = h ? p[3].y : p[3].x;
            float v4 = h ? p[4].y : p[4].x;
            float v5 = h ? p[5].y : p[5].x;
            float v6 = h ? p[6].y : p[6].x;
            float v7 = h ? p[7].y : p[7].x;

            // bias as separately rounded add (matches x@W.T + b)
            float4 cur0 = make_float4(__fadd_rn(v0, bb0.x), __fadd_rn(v1, bb0.y),
                                      __fadd_rn(v2, bb0.z), __fadd_rn(v3, bb0.w));
            float4 cur1 = make_float4(__fadd_rn(v4, bb1.x), __fadd_rn(v5, bb1.y),
                                      __fadd_rn(v6, bb1.z), __fadd_rn(v7, bb1.w));

            size_t i0 = (size_t)r * N + col0;
            size_t i1 = (size_t)r * N + col1;

            if constexpr (MODE == 0) {
                *(float4*)(Ccur + i0) = cur0;
                *(float4*)(Ccur + i1) = cur1;
            } else {
                float4 m0 = *(const float4*)(Mst + i0);
                float4 m1 = *(const float4*)(Mst + i1);
                float4 s0, s1;
                lif_step(m0.x, cur0.x, s0.x); lif_step(m0.y, cur0.y, s0.y);
                lif_step(m0.z, cur0.z, s0.z); lif_step(m0.w, cur0.w, s0.w);
                lif_step(m1.x, cur1.x, s1.x); lif_step(m1.y, cur1.y, s1.y);
                lif_step(m1.z, cur1.z, s1.z); lif_step(m1.w, cur1.w, s1.w);
                *(float4*)(Mst + i0) = m0;
                *(float4*)(Mst + i1) = m1;
                if constexpr (MODE == 1) {
                    *(float4*)(Sout + i0) = s0;
                    *(float4*)(Sout + i1) = s1;
                } else {
                    float4 o0 = *(const float4*)(Oacc + i0);
                    float4 o1 = *(const float4*)(Oacc + i1);
                    o0.x = __fmul_rn(__fadd_rn(o0.x, s0.x), outScale);
                    o0.y = __fmul_rn(__fadd_rn(o0.y, s0.y), outScale);
                    o0.z = __fmul_rn(__fadd_rn(o0.z, s0.z), outScale);
                    o0.w = __fmul_rn(__fadd_rn(o0.w, s0.w), outScale);
                    o1.x = __fmul_rn(__fadd_rn(o1.x, s1.x), outScale);
                    o1.y = __fmul_rn(__fadd_rn(o1.y, s1.y), outScale);
                    o1.z = __fmul_rn(__fadd_rn(o1.z, s1.z), outScale);
                    o1.w = __fmul_rn(__fadd_rn(o1.w, s1.w), outScale);
                    *(float4*)(Oacc + i0) = o0;
                    *(float4*)(Oacc + i1) = o1;
                }
            }
        }
    }
}

// elementwise LIF for layer 1 (cur1 is precomputed and constant over steps)
__global__ void lif1_kernel(const float* __restrict__ cur,
                            float* __restrict__ Mst,
                            float* __restrict__ S, int n4)
{
    int i = blockIdx.x * blockDim.x + threadIdx.x;
    if (i >= n4) return;
    float4 c = ((const float4*)cur)[i];
    float4 m = ((const float4*)Mst)[i];
    float4 s;
    lif_step(m.x, c.x, s.x);
    lif_step(m.y, c.y, s.y);
    lif_step(m.z, c.z, s.z);
    lif_step(m.w, c.w, s.w);
    ((float4*)Mst)[i] = m;
    ((float4*)S)[i]   = s;
}

// zero membranes + output (d_out arrives poisoned)
__global__ void init_kernel(float* __restrict__ out, int nBH4, int nBD4)
{
    int i = blockIdx.x * blockDim.x + threadIdx.x;
    float4 z = make_float4(0.f, 0.f, 0.f, 0.f);
    if (i < nBD4) {
        ((float4*)out)[i]  = z;
        ((float4*)g_m3)[i] = z;
    }
    if (i < nBH4) {
        ((float4*)g_m1)[i] = z;
        ((float4*)g_m2)[i] = z;
    }
}

extern "C" void kernel_launch(void* const* d_in, const int* in_sizes, int n_in,
                              void* d_out, int out_size)
{
    const float* x  = (const float*)d_in[0];
    const float* W1 = (const float*)d_in[1];
    const float* b1 = (const float*)d_in[2];
    const float* W2 = (const float*)d_in[3];
    const float* b2 = (const float*)d_in[4];
    const float* W3 = (const float*)d_in[5];
    const float* b3 = (const float*)d_in[6];

    const int H = in_sizes[2];          // 512
    const int D = in_sizes[6];          // 1024
    const int B = in_sizes[0] / D;      // 16384
    float* out = (float*)d_out;

    float *cur1, *m1, *m2, *m3, *s1, *s2;
    cudaGetSymbolAddress((void**)&cur1, g_cur1);
    cudaGetSymbolAddress((void**)&m1,   g_m1);
    cudaGetSymbolAddress((void**)&m2,   g_m2);
    cudaGetSymbolAddress((void**)&m3,   g_m3);
    cudaGetSymbolAddress((void**)&s1,   g_s1);
    cudaGetSymbolAddress((void**)&s2,   g_s2);

    const int nBH4 = (B * H) / 4;
    const int nBD4 = (B * D) / 4;

    init_kernel<<<(nBD4 + 255) / 256, 256>>>(out, nBH4, nBD4);

    // fc1(x): constant over timesteps
    gemm_lif<0><<<dim3(H / 128, B / 128), 256>>>(
        x, W1, b1, cur1, nullptr, nullptr, nullptr, 1.0f, B, H, D);

    for (int t = 0; t < T_STEPS; t++) {
        lif1_kernel<<<(nBH4 + 255) / 256, 256>>>(cur1, m1, s1, nBH4);

        gemm_lif<1><<<dim3(H / 128, B / 128), 256>>>(
            s1, W2, b2, nullptr, m2, s2, nullptr, 1.0f, B, H, H);

        float sc = (t == T_STEPS - 1) ? (1.0f / (float)T_STEPS) : 1.0f;
        gemm_lif<2><<<dim3(D / 128, B / 128), 256>>>(
            s2, W3, b3, nullptr, m3, nullptr, out, sc, B, D, H);
    }
}

// round 15
// speedup vs baseline: 1.9554x; 1.9554x over previous
#include <cuda_runtime.h>

typedef unsigned long long u64;

#define BETA 0.95f
#define THRV 1.0f
#define KC   512              // fc1: two 512-halves folded; K=512 stays pure chain

static const int T_STEPS = 10;
static const int MAXB = 16384, MAXH = 512, MAXD = 1024;

// ---- persistent state (device globals; no runtime allocation allowed) ----
__device__ float g_cur1[MAXB * MAXH];   // fc1(x), computed once per launch
__device__ float g_m1[MAXB * MAXH];
__device__ float g_m2[MAXB * MAXH];
__device__ float g_m3[MAXB * MAXD];
__device__ float g_s1[MAXB * MAXH];
__device__ float g_s2[MAXB * MAXH];

// ---- f32x2 packed math (lane-wise identical rounding to scalar ops) ----
__device__ __forceinline__ float2 upk2(u64 v) {
    float2 f;
    asm("mov.b64 {%0, %1}, %2;" : "=f"(f.x), "=f"(f.y) : "l"(v));
    return f;
}
__device__ __forceinline__ u64 pk2(float x, float y) {
    u64 r;
    asm("mov.b64 %0, {%1, %2};" : "=l"(r) : "f"(x), "f"(y));
    return r;
}
__device__ __forceinline__ void ffma2(u64& d, u64 a, u64 b) {
    asm("fma.rn.f32x2 %0, %1, %2, %0;" : "+l"(d) : "l"(a), "l"(b));
}
__device__ __forceinline__ void fadd2(u64& d, u64 a) {
    asm("add.rn.f32x2 %0, %0, %1;" : "+l"(d) : "l"(a));
}

// LIF update, NO FMA contraction: m' = rn(rn(rn(beta*m) + cur) - reset)
__device__ __forceinline__ void lif_step(float& m, float cur, float& s) {
    float reset = (m > THRV) ? THRV : 0.0f;   // reset uses PREVIOUS mem
    float t0 = __fmul_rn(BETA, m);
    float t1 = __fadd_rn(t0, cur);
    m = __fsub_rn(t1, reset);
    s = (m > THRV) ? 1.0f : 0.0f;
}

// ============================================================================
// Fused GEMM:  C[M,N] = A[M,K] @ W[N,K]^T (+bias) -> epilogue per MODE
//   MODE 0: write cur     MODE 1: LIF -> Mst,Sout    MODE 2: LIF -> Oacc
// Tile BM=128, BN=128, BK=8, 256 threads, 8 rows x 8 cols per thread.
// COLUMN-PAIR f32x2 packing: acc lanes = (col j, col j+1); per output lane the
// accumulation is bitwise an ascending-k scalar FMA chain, with the KC=512
// panel fold (FOLD=true) reproducing the reference ordering exactly.
// Double-buffered smem, one __syncthreads per 8-k stage, global prefetch.
// ============================================================================
template<int MODE, bool FOLD>
__global__ __launch_bounds__(256, FOLD ? 1 : 2)
void gemm_lif(const float* __restrict__ A, const float* __restrict__ W,
              const float* __restrict__ bias,
              float* __restrict__ Ccur,
              float* __restrict__ Mst,
              float* __restrict__ Sout,
              float* __restrict__ Oacc,
              float outScale,
              int M, int N, int K)
{
    __shared__ __align__(16) u64   As2[2][8][130];  // [buf][k][row] = (a,a) dup
    __shared__ __align__(16) float Bs [2][8][132];  // [buf][k][col]

    const int tid = threadIdx.x;
    const int tx  = tid & 15;         // column group 0..15
    const int ty  = tid >> 4;         // row group    0..15

    const int bm = blockIdx.y * 128;
    const int bn = blockIdx.x * 128;

    const int lr = tid >> 1;          // 0..127 (one A row / one B col)
    const int lk = (tid & 1) << 2;    // 0 or 4

    const float* Ag = A + (size_t)(bm + lr) * K + lk;
    const float* Wg = W + (size_t)(bn + lr) * K + lk;

    u64 acc[8][4];                    // [row r][colpair jp]
    u64 accT[8][4];                   // folded total (FOLD only; else unused)
    #pragma unroll
    for (int r = 0; r < 8; r++)
        #pragma unroll
        for (int j = 0; j < 4; j++) { acc[r][j] = 0ull; accT[r][j] = 0ull; }

    // prefetch + store stage 0
    float4 an = *(const float4*)Ag;
    float4 wn = *(const float4*)Wg;
    As2[0][lk+0][lr] = pk2(an.x, an.x);
    As2[0][lk+1][lr] = pk2(an.y, an.y);
    As2[0][lk+2][lr] = pk2(an.z, an.z);
    As2[0][lk+3][lr] = pk2(an.w, an.w);
    Bs [0][lk+0][lr] = wn.x;
    Bs [0][lk+1][lr] = wn.y;
    Bs [0][lk+2][lr] = wn.z;
    Bs [0][lk+3][lr] = wn.w;

    const int nT = K >> 3;
    for (int t = 0; t < nT; t++) {
        const int cur = t & 1;
        __syncthreads();              // stage t stores visible; stage t-1 compute done

        const bool more = (t + 1 < nT);
        if (more) {
            an = *(const float4*)(Ag + (t + 1) * 8);
            wn = *(const float4*)(Wg + (t + 1) * 8);
        }

        #pragma unroll
        for (int k = 0; k < 8; k++) {
            ulonglong2 a01 = *(const ulonglong2*)&As2[cur][k][ty * 8 + 0];
            ulonglong2 a23 = *(const ulonglong2*)&As2[cur][k][ty * 8 + 2];
            ulonglong2 a45 = *(const ulonglong2*)&As2[cur][k][ty * 8 + 4];
            ulonglong2 a67 = *(const ulonglong2*)&As2[cur][k][ty * 8 + 6];
            u64 ar[8] = { a01.x, a01.y, a23.x, a23.y,
                          a45.x, a45.y, a67.x, a67.y };
            ulonglong2 b01 = *(const ulonglong2*)&Bs[cur][k][4 * tx];
            ulonglong2 b23 = *(const ulonglong2*)&Bs[cur][k][64 + 4 * tx];
            u64 bp[4] = { b01.x, b01.y, b23.x, b23.y };
            #pragma unroll
            for (int r = 0; r < 8; r++)
                #pragma unroll
                for (int j = 0; j < 4; j++)
                    ffma2(acc[r][j], ar[r], bp[j]);
        }

        if constexpr (FOLD) {
            // KC-panel boundary (mid-loop only; final fold after the loop)
            if ((((t + 1) << 3) % KC) == 0 && (t + 1) < nT) {
                #pragma unroll
                for (int r = 0; r < 8; r++)
                    #pragma unroll
                    for (int j = 0; j < 4; j++) {
                        fadd2(accT[r][j], acc[r][j]);
                        acc[r][j] = 0ull;
                    }
            }
        }

        if (more) {
            const int nxt = cur ^ 1;
            As2[nxt][lk+0][lr] = pk2(an.x, an.x);
            As2[nxt][lk+1][lr] = pk2(an.y, an.y);
            As2[nxt][lk+2][lr] = pk2(an.z, an.z);
            As2[nxt][lk+3][lr] = pk2(an.w, an.w);
            Bs [nxt][lk+0][lr] = wn.x;
            Bs [nxt][lk+1][lr] = wn.y;
            Bs [nxt][lk+2][lr] = wn.z;
            Bs [nxt][lk+3][lr] = wn.w;
        }
    }

    if constexpr (FOLD) {
        // final fold: C = rn(S0 + S1)
        #pragma unroll
        for (int r = 0; r < 8; r++)
            #pragma unroll
            for (int j = 0; j < 4; j++)
                fadd2(accT[r][j], acc[r][j]);
    }

    // ---- epilogue ----
    const int col0 = bn + 4 * tx;
    const int col1 = col0 + 64;
    float4 bb0 = *(const float4*)(bias + col0);
    float4 bb1 = *(const float4*)(bias + col1);

    #pragma unroll
    for (int r = 0; r < 8; r++) {
        const int row = bm + ty * 8 + r;
        float2 p0, p1, p2, p3;
        if constexpr (FOLD) {
            p0 = upk2(accT[r][0]); p1 = upk2(accT[r][1]);
            p2 = upk2(accT[r][2]); p3 = upk2(accT[r][3]);
        } else {
            p0 = upk2(acc[r][0]);  p1 = upk2(acc[r][1]);
            p2 = upk2(acc[r][2]);  p3 = upk2(acc[r][3]);
        }

        // bias as separately rounded add (matches x@W.T + b)
        float4 cur0 = make_float4(__fadd_rn(p0.x, bb0.x), __fadd_rn(p0.y, bb0.y),
                                  __fadd_rn(p1.x, bb0.z), __fadd_rn(p1.y, bb0.w));
        float4 cur1 = make_float4(__fadd_rn(p2.x, bb1.x), __fadd_rn(p2.y, bb1.y),
                                  __fadd_rn(p3.x, bb1.z), __fadd_rn(p3.y, bb1.w));

        size_t i0 = (size_t)row * N + col0;
        size_t i1 = (size_t)row * N + col1;

        if constexpr (MODE == 0) {
            *(float4*)(Ccur + i0) = cur0;
            *(float4*)(Ccur + i1) = cur1;
        } else {
            float4 m0 = *(const float4*)(Mst + i0);
            float4 m1 = *(const float4*)(Mst + i1);
            float4 s0, s1;
            lif_step(m0.x, cur0.x, s0.x); lif_step(m0.y, cur0.y, s0.y);
            lif_step(m0.z, cur0.z, s0.z); lif_step(m0.w, cur0.w, s0.w);
            lif_step(m1.x, cur1.x, s1.x); lif_step(m1.y, cur1.y, s1.y);
            lif_step(m1.z, cur1.z, s1.z); lif_step(m1.w, cur1.w, s1.w);
            *(float4*)(Mst + i0) = m0;
            *(float4*)(Mst + i1) = m1;
            if constexpr (MODE == 1) {
                *(float4*)(Sout + i0) = s0;
                *(float4*)(Sout + i1) = s1;
            } else {
                float4 o0 = *(const float4*)(Oacc + i0);
                float4 o1 = *(const float4*)(Oacc + i1);
                o0.x = __fmul_rn(__fadd_rn(o0.x, s0.x), outScale);
                o0.y = __fmul_rn(__fadd_rn(o0.y, s0.y), outScale);
                o0.z = __fmul_rn(__fadd_rn(o0.z, s0.z), outScale);
                o0.w = __fmul_rn(__fadd_rn(o0.w, s0.w), outScale);
                o1.x = __fmul_rn(__fadd_rn(o1.x, s1.x), outScale);
                o1.y = __fmul_rn(__fadd_rn(o1.y, s1.y), outScale);
                o1.z = __fmul_rn(__fadd_rn(o1.z, s1.z), outScale);
                o1.w = __fmul_rn(__fadd_rn(o1.w, s1.w), outScale);
                *(float4*)(Oacc + i0) = o0;
                *(float4*)(Oacc + i1) = o1;
            }
        }
    }
}

// elementwise LIF for layer 1 (cur1 is precomputed and constant over steps)
__global__ void lif1_kernel(const float* __restrict__ cur,
                            float* __restrict__ Mst,
                            float* __restrict__ S, int n4)
{
    int i = blockIdx.x * blockDim.x + threadIdx.x;
    if (i >= n4) return;
    float4 c = ((const float4*)cur)[i];
    float4 m = ((const float4*)Mst)[i];
    float4 s;
    lif_step(m.x, c.x, s.x);
    lif_step(m.y, c.y, s.y);
    lif_step(m.z, c.z, s.z);
    lif_step(m.w, c.w, s.w);
    ((float4*)Mst)[i] = m;
    ((float4*)S)[i]   = s;
}

// zero membranes + output (d_out arrives poisoned)
__global__ void init_kernel(float* __restrict__ out, int nBH4, int nBD4)
{
    int i = blockIdx.x * blockDim.x + threadIdx.x;
    float4 z = make_float4(0.f, 0.f, 0.f, 0.f);
    if (i < nBD4) {
        ((float4*)out)[i]  = z;
        ((float4*)g_m3)[i] = z;
    }
    if (i < nBH4) {
        ((float4*)g_m1)[i] = z;
        ((float4*)g_m2)[i] = z;
    }
}

extern "C" void kernel_launch(void* const* d_in, const int* in_sizes, int n_in,
                              void* d_out, int out_size)
{
    const float* x  = (const float*)d_in[0];
    const float* W1 = (const float*)d_in[1];
    const float* b1 = (const float*)d_in[2];
    const float* W2 = (const float*)d_in[3];
    const float* b2 = (const float*)d_in[4];
    const float* W3 = (const float*)d_in[5];
    const float* b3 = (const float*)d_in[6];

    const int H = in_sizes[2];          // 512
    const int D = in_sizes[6];          // 1024
    const int B = in_sizes[0] / D;      // 16384
    float* out = (float*)d_out;

    float *cur1, *m1, *m2, *m3, *s1, *s2;
    cudaGetSymbolAddress((void**)&cur1, g_cur1);
    cudaGetSymbolAddress((void**)&m1,   g_m1);
    cudaGetSymbolAddress((void**)&m2,   g_m2);
    cudaGetSymbolAddress((void**)&m3,   g_m3);
    cudaGetSymbolAddress((void**)&s1,   g_s1);
    cudaGetSymbolAddress((void**)&s2,   g_s2);

    const int nBH4 = (B * H) / 4;
    const int nBD4 = (B * D) / 4;

    init_kernel<<<(nBD4 + 255) / 256, 256>>>(out, nBH4, nBD4);

    // fc1(x): K=1024 -> KC=512 fold; constant over timesteps
    gemm_lif<0, true><<<dim3(H / 128, B / 128), 256>>>(
        x, W1, b1, cur1, nullptr, nullptr, nullptr, 1.0f, B, H, D);

    for (int t = 0; t < T_STEPS; t++) {
        lif1_kernel<<<(nBH4 + 255) / 256, 256>>>(cur1, m1, s1, nBH4);

        gemm_lif<1, false><<<dim3(H / 128, B / 128), 256>>>(
            s1, W2, b2, nullptr, m2, s2, nullptr, 1.0f, B, H, H);

        float sc = (t == T_STEPS - 1) ? (1.0f / (float)T_STEPS) : 1.0f;
        gemm_lif<2, false><<<dim3(D / 128, B / 128), 256>>>(
            s2, W3, b3, nullptr, m3, nullptr, out, sc, B, D, H);
    }
}